// round 1
// baseline (speedup 1.0000x reference)
#include <cuda_runtime.h>
#include <math.h>

#define NN 50000
#define NE 400000
#define DIN 256
#define EMB 256
#define NH 8
#define HD 32

// ---------------- scratch (device globals; no runtime alloc) ----------------
__device__ float    g_Pi[(size_t)NN * EMB];     // nodes @ Wi + bi
__device__ float    g_Pj[(size_t)NN * EMB];     // nodes @ Wj + bj
__device__ float    g_logits[(size_t)NE * NH];
__device__ float    g_wun[(size_t)NE * NH];     // exp(logit - max)
__device__ float    g_denom[(size_t)NN * NH];
__device__ unsigned g_nmax[(size_t)NN * NH];    // ordered-uint encoded float max

// float <-> order-preserving uint
__device__ __forceinline__ unsigned fenc(float f) {
    unsigned u = __float_as_uint(f);
    return (u & 0x80000000u) ? ~u : (u | 0x80000000u);
}
__device__ __forceinline__ float fdec(unsigned u) {
    unsigned b = (u & 0x80000000u) ? (u ^ 0x80000000u) : ~u;
    return __uint_as_float(b);
}

// ---------------- init: zero out/denom, -inf max ----------------
__global__ void init_kernel(float* __restrict__ out) {
    int i = blockIdx.x * blockDim.x + threadIdx.x;
    int stride = gridDim.x * blockDim.x;
    for (int j = i; j < NN * EMB; j += stride) out[j] = 0.0f;
    for (int j = i; j < NN * NH; j += stride) {
        g_denom[j] = 0.0f;
        g_nmax[j] = 0x007FFFFFu;   // fenc(-inf)
    }
}

// ---------------- projection GEMM: P = nodes @ W + b ----------------
// BM=128, BN=64, BK=16, 256 threads, each computes 8x4
__global__ __launch_bounds__(256) void proj_kernel(
    const float* __restrict__ A,
    const float* __restrict__ Wi, const float* __restrict__ bi,
    const float* __restrict__ Wj, const float* __restrict__ bj)
{
    __shared__ float As[16][128];   // [k][m] transposed
    __shared__ float Bs[16][64];    // [k][n]

    int tid = threadIdx.x;
    int bm = blockIdx.x * 128;
    int bn0 = blockIdx.y * 64;

    const float* B; const float* bias; float* P;
    if (bn0 < 256) { B = Wi; bias = bi; P = g_Pi; }
    else           { B = Wj; bias = bj; P = g_Pj; bn0 -= 256; }

    int tx = tid & 15;          // N dir (x4)
    int ty = tid >> 4;          // M dir (x8)

    int ar = tid >> 2;          // 0..63  (A tile row within half)
    int ac = (tid & 3) * 4;     // 0,4,8,12
    int br = tid >> 4;          // 0..15
    int bc = (tid & 15) * 4;    // 0..60

    float acc[8][4];
#pragma unroll
    for (int i = 0; i < 8; i++)
#pragma unroll
        for (int j = 0; j < 4; j++) acc[i][j] = 0.0f;

    for (int k0 = 0; k0 < DIN; k0 += 16) {
        // load A tile (128x16) transposed into As[k][m]
#pragma unroll
        for (int i = 0; i < 2; i++) {
            int row = bm + ar + i * 64;
            float4 v = make_float4(0.f, 0.f, 0.f, 0.f);
            if (row < NN) v = *(const float4*)(A + (size_t)row * DIN + k0 + ac);
            As[ac + 0][ar + i * 64] = v.x;
            As[ac + 1][ar + i * 64] = v.y;
            As[ac + 2][ar + i * 64] = v.z;
            As[ac + 3][ar + i * 64] = v.w;
        }
        // load B tile (16x64)
        {
            float4 v = *(const float4*)(B + (size_t)(k0 + br) * 256 + bn0 + bc);
            *(float4*)&Bs[br][bc] = v;
        }
        __syncthreads();

#pragma unroll
        for (int k = 0; k < 16; k++) {
            float4 a0 = *(const float4*)&As[k][ty * 8];
            float4 a1 = *(const float4*)&As[k][ty * 8 + 4];
            float4 bv = *(const float4*)&Bs[k][tx * 4];
            float a[8] = {a0.x, a0.y, a0.z, a0.w, a1.x, a1.y, a1.z, a1.w};
            float b[4] = {bv.x, bv.y, bv.z, bv.w};
#pragma unroll
            for (int i = 0; i < 8; i++)
#pragma unroll
                for (int j = 0; j < 4; j++) acc[i][j] += a[i] * b[j];
        }
        __syncthreads();
    }

#pragma unroll
    for (int i = 0; i < 8; i++) {
        int row = bm + ty * 8 + i;
        if (row < NN) {
            int col = bn0 + tx * 4;
            float4 o;
            o.x = acc[i][0] + bias[col + 0];
            o.y = acc[i][1] + bias[col + 1];
            o.z = acc[i][2] + bias[col + 2];
            o.w = acc[i][3] + bias[col + 3];
            *(float4*)(P + (size_t)row * 256 + col) = o;
        }
    }
}

// ---------------- edge logits: one warp per edge ----------------
// lane l owns k=l across all 8 heads -> 128B coalesced loads per head
__global__ __launch_bounds__(256) void edge_logits_kernel(
    const int* __restrict__ senders, const int* __restrict__ receivers,
    const float* __restrict__ a_w, const float* __restrict__ a_b)
{
    int warp = (blockIdx.x * blockDim.x + threadIdx.x) >> 5;
    int lane = threadIdx.x & 31;
    if (warp >= NE) return;

    int s = senders[warp];
    int r = receivers[warp];
    float aw = a_w[lane];
    float ab = a_b[0];
    const float* pi = g_Pi + (size_t)s * 256;
    const float* pj = g_Pj + (size_t)r * 256;

    float p[NH];
#pragma unroll
    for (int h = 0; h < NH; h++) {
        float x = pi[h * 32 + lane] + pj[h * 32 + lane];
        // mish(x) = x * tanh(softplus(x)), stable softplus
        float sp = fmaxf(x, 0.0f) + log1pf(__expf(-fabsf(x)));
        float m = x * tanhf(sp);
        p[h] = m * aw;
    }
#pragma unroll
    for (int off = 16; off > 0; off >>= 1)
#pragma unroll
        for (int h = 0; h < NH; h++)
            p[h] += __shfl_xor_sync(0xffffffffu, p[h], off);

    if (lane == 0) {
#pragma unroll
        for (int h = 0; h < NH; h++) {
            float v = p[h] + ab;
            g_logits[(size_t)warp * NH + h] = v;
            atomicMax(&g_nmax[(size_t)r * NH + h], fenc(v));
        }
    }
}

// ---------------- exp + denom: one thread per (edge, head) ----------------
__global__ __launch_bounds__(256) void edge_exp_kernel(const int* __restrict__ receivers)
{
    int i = blockIdx.x * blockDim.x + threadIdx.x;
    if (i >= NE * NH) return;
    int e = i >> 3;
    int h = i & 7;
    int r = receivers[e];
    float m = fdec(g_nmax[(size_t)r * NH + h]);
    float v = __expf(g_logits[i] - m);
    g_wun[i] = v;
    atomicAdd(&g_denom[(size_t)r * NH + h], v);
}

// ---------------- weighted aggregation: one warp per edge ----------------
__global__ __launch_bounds__(256) void edge_agg_kernel(
    const int* __restrict__ senders, const int* __restrict__ receivers,
    float* __restrict__ out)
{
    int warp = (blockIdx.x * blockDim.x + threadIdx.x) >> 5;
    int lane = threadIdx.x & 31;
    if (warp >= NE) return;

    int s = senders[warp];
    int r = receivers[warp];
    const float* pi = g_Pi + (size_t)s * 256;
    float* o = out + (size_t)r * 256;

    float tmp = 0.0f;
    if (lane < NH)
        tmp = g_wun[(size_t)warp * NH + lane] / g_denom[(size_t)r * NH + lane];
    float w[NH];
#pragma unroll
    for (int h = 0; h < NH; h++)
        w[h] = __shfl_sync(0xffffffffu, tmp, h);

#pragma unroll
    for (int h = 0; h < NH; h++)
        atomicAdd(&o[h * 32 + lane], pi[h * 32 + lane] * w[h]);
}

// ---------------- launch ----------------
extern "C" void kernel_launch(void* const* d_in, const int* in_sizes, int n_in,
                              void* d_out, int out_size)
{
    const float* nodes     = (const float*)d_in[0];
    const int*   senders   = (const int*)d_in[1];
    const int*   receivers = (const int*)d_in[2];
    const float* Wi        = (const float*)d_in[3];
    const float* bi        = (const float*)d_in[4];
    const float* Wj        = (const float*)d_in[5];
    const float* bj        = (const float*)d_in[6];
    const float* a_w       = (const float*)d_in[7];
    const float* a_b       = (const float*)d_in[8];
    float* out = (float*)d_out;

    init_kernel<<<512, 256>>>(out);

    dim3 gproj((NN + 127) / 128, 8);
    proj_kernel<<<gproj, 256>>>(nodes, Wi, bi, Wj, bj);

    edge_logits_kernel<<<(NE * 32) / 256, 256>>>(senders, receivers, a_w, a_b);

    edge_exp_kernel<<<(NE * NH + 255) / 256, 256>>>(receivers);

    edge_agg_kernel<<<(NE * 32) / 256, 256>>>(senders, receivers, out);
}

// round 3
// speedup vs baseline: 1.2497x; 1.2497x over previous
#include <cuda_runtime.h>
#include <cuda_bf16.h>
#include <cstdint>
#include <math.h>

#define NN 50000
#define NE 400000
#define DIN 256
#define EMB 256
#define NH 8
#define HD 32

// ---------------- scratch (device globals; no runtime alloc) ----------------
__device__ __align__(16) float    g_Pi[(size_t)NN * EMB];
__device__ __align__(16) float    g_Pj[(size_t)NN * EMB];
__device__ __align__(16) float    g_logits[(size_t)NE * NH];
__device__ __align__(16) float    g_wun[(size_t)NE * NH];
__device__ __align__(16) float    g_denom[(size_t)NN * NH];
__device__ __align__(16) unsigned g_nmax[(size_t)NN * NH];

// split-bf16 operands for tensor-core GEMM
__device__ __align__(16) __nv_bfloat16 g_Ahi[(size_t)NN * DIN];
__device__ __align__(16) __nv_bfloat16 g_Alo[(size_t)NN * DIN];
__device__ __align__(16) __nv_bfloat16 g_Bhi[(size_t)512 * DIN];  // [n_global][k]
__device__ __align__(16) __nv_bfloat16 g_Blo[(size_t)512 * DIN];

// ---------------- helpers ----------------
__device__ __forceinline__ uint32_t smem_u32(const void* p) {
    uint32_t a;
    asm("{ .reg .u64 t; cvta.to.shared.u64 t, %1; cvt.u32.u64 %0, t; }" : "=r"(a) : "l"(p));
    return a;
}
__device__ __forceinline__ uint32_t sw128(uint32_t off) { return off ^ ((off >> 3) & 0x70); }

__device__ __forceinline__ void ldsm_x4(uint32_t* r, uint32_t addr) {
    asm volatile("ldmatrix.sync.aligned.m8n8.x4.shared.b16 {%0,%1,%2,%3}, [%4];"
                 : "=r"(r[0]), "=r"(r[1]), "=r"(r[2]), "=r"(r[3]) : "r"(addr));
}
__device__ __forceinline__ void mma16816(float* c, const uint32_t* a, const uint32_t* b) {
    asm volatile("mma.sync.aligned.m16n8k16.row.col.f32.bf16.bf16.f32 "
                 "{%0,%1,%2,%3}, {%4,%5,%6,%7}, {%8,%9}, {%0,%1,%2,%3};"
                 : "+f"(c[0]), "+f"(c[1]), "+f"(c[2]), "+f"(c[3])
                 : "r"(a[0]), "r"(a[1]), "r"(a[2]), "r"(a[3]), "r"(b[0]), "r"(b[1]));
}
#define STS128A(addr, v) \
    asm volatile("st.shared.v4.b32 [%0], {%1, %2, %3, %4};" \
        :: "r"(addr), "r"((v).x), "r"((v).y), "r"((v).z), "r"((v).w) : "memory")

// float <-> order-preserving uint
__device__ __forceinline__ unsigned fenc(float f) {
    unsigned u = __float_as_uint(f);
    return (u & 0x80000000u) ? ~u : (u | 0x80000000u);
}
__device__ __forceinline__ float fdec(unsigned u) {
    unsigned b = (u & 0x80000000u) ? (u ^ 0x80000000u) : ~u;
    return __uint_as_float(b);
}

// ---------------- init ----------------
__global__ void init_kernel(float* __restrict__ out) {
    int i = blockIdx.x * blockDim.x + threadIdx.x;
    int stride = gridDim.x * blockDim.x;
    for (int j = i; j < NN * EMB; j += stride) out[j] = 0.0f;
    for (int j = i; j < NN * NH; j += stride) {
        g_denom[j] = 0.0f;
        g_nmax[j] = 0x007FFFFFu;  // fenc(-inf)
    }
}

// ---------------- pre-split nodes into bf16 hi/lo ----------------
__global__ __launch_bounds__(256) void presplit_nodes(const float* __restrict__ nodes) {
    size_t i = (size_t)blockIdx.x * blockDim.x + threadIdx.x;   // unit of 8 floats
    size_t total = (size_t)NN * DIN / 8;
    if (i >= total) return;
    const float4* src = (const float4*)nodes + i * 2;
    float4 v0 = src[0], v1 = src[1];
    float f[8] = {v0.x, v0.y, v0.z, v0.w, v1.x, v1.y, v1.z, v1.w};
    alignas(16) __nv_bfloat16 h[8];
    alignas(16) __nv_bfloat16 l[8];
#pragma unroll
    for (int j = 0; j < 8; j++) {
        h[j] = __float2bfloat16(f[j]);
        l[j] = __float2bfloat16(f[j] - __bfloat162float(h[j]));
    }
    *(uint4*)(g_Ahi + i * 8) = *(uint4*)h;
    *(uint4*)(g_Alo + i * 8) = *(uint4*)l;
}

// ---------------- pre-split + transpose W into [n][k] bf16 hi/lo ----------------
__global__ __launch_bounds__(256) void presplit_W(const float* __restrict__ Wi,
                                                  const float* __restrict__ Wj) {
    int idx = blockIdx.x * blockDim.x + threadIdx.x;
    if (idx >= 512 * 256) return;
    int n = idx >> 8, k = idx & 255;
    const float* W = (n < 256) ? Wi : Wj;
    int col = n & 255;
    float x = W[(size_t)k * 256 + col];
    __nv_bfloat16 h = __float2bfloat16(x);
    __nv_bfloat16 l = __float2bfloat16(x - __bfloat162float(h));
    g_Bhi[(size_t)n * 256 + k] = h;
    g_Blo[(size_t)n * 256 + k] = l;
}

// ---------------- tensor-core projection GEMM (mma.sync / HMMA) ----------------
// P[m, n] = sum_k A[m,k] * W[k,n];  split-bf16: AhBh + AhBl + AlBh, fp32 accum.
// CTA tile 128(M) x 128(N), K-chunk 64, 512 threads, warp tile 32x32.
__global__ __launch_bounds__(512) void gemm_mma(const float* __restrict__ bi,
                                                const float* __restrict__ bj) {
    extern __shared__ char dsm[];
    uint32_t base = (smem_u32(dsm) + 1023) & ~1023u;
    uint32_t sAh = base, sAl = base + 16384, sBh = base + 32768, sBl = base + 49152;

    int tid = threadIdx.x, wid = tid >> 5, lane = tid & 31;
    int warp_m = wid & 3, warp_n = wid >> 2;     // 4 x 4 warps
    int m_base = warp_m * 32, n_base = warp_n * 32;
    int m0 = blockIdx.x * 128;
    int ntile = blockIdx.y;
    size_t brow0 = (size_t)ntile * 128 * 256;    // base row of g_B for this n-tile

    float acc[2][4][4];
#pragma unroll
    for (int i = 0; i < 2; i++)
#pragma unroll
        for (int j = 0; j < 4; j++)
#pragma unroll
            for (int q = 0; q < 4; q++) acc[i][j][q] = 0.0f;

    for (int kc = 0; kc < 4; kc++) {
        int k0 = kc * 64;
        __syncthreads();   // protect smem from previous iter's readers
        // stage 128x64 bf16 tiles (A hi/lo, B hi/lo), SW128-swizzled 128B rows
#pragma unroll
        for (int u = tid; u < 1024; u += 512) {
            int r = u >> 3, g = u & 7;
            uint32_t off = sw128((uint32_t)(r * 128 + g * 16));
            uint4 vh = make_uint4(0, 0, 0, 0), vl = make_uint4(0, 0, 0, 0);
            int row = m0 + r;
            if (row < NN) {
                size_t s = (size_t)row * 256 + k0 + g * 8;
                vh = *(const uint4*)(g_Ahi + s);
                vl = *(const uint4*)(g_Alo + s);
            }
            STS128A(sAh + off, vh);
            STS128A(sAl + off, vl);
            size_t sb = brow0 + (size_t)r * 256 + k0 + g * 8;
            uint4 wh = *(const uint4*)(g_Bhi + sb);
            uint4 wl = *(const uint4*)(g_Blo + sb);
            STS128A(sBh + off, wh);
            STS128A(sBl + off, wl);
        }
        __syncthreads();

#pragma unroll
        for (int ks = 0; ks < 4; ks++) {
            // A fragments: 2 m16 tiles, hi & lo
            uint32_t ah[2][4], al[2][4];
#pragma unroll
            for (int mi = 0; mi < 2; mi++) {
                uint32_t off = sw128((uint32_t)((m_base + mi * 16 + (lane & 15)) * 128 +
                                                ks * 32 + (lane >> 4) * 16));
                ldsm_x4(ah[mi], sAh + off);
                ldsm_x4(al[mi], sAl + off);
            }
            // B fragments: 2 x4 loads each cover two n8 blocks (hi & lo)
            uint32_t bh[8], bl[8];
#pragma unroll
            for (int np = 0; np < 2; np++) {
                int g = lane >> 3;
                int nrow = n_base + np * 16 + (lane & 7) + ((g & 2) ? 8 : 0);
                uint32_t off = sw128((uint32_t)(nrow * 128 + ks * 32 + (g & 1) * 16));
                ldsm_x4(&bh[np * 4], sBh + off);
                ldsm_x4(&bl[np * 4], sBl + off);
            }
#pragma unroll
            for (int mi = 0; mi < 2; mi++)
#pragma unroll
                for (int nb = 0; nb < 4; nb++) {
                    const int bo = (nb >> 1) * 4 + (nb & 1) * 2;
                    mma16816(acc[mi][nb], ah[mi], &bh[bo]);
                    mma16816(acc[mi][nb], ah[mi], &bl[bo]);
                    mma16816(acc[mi][nb], al[mi], &bh[bo]);
                }
        }
    }

    // epilogue: add bias, store fp32
    float* P = (ntile < 2) ? g_Pi : g_Pj;
    const float* bias = (ntile < 2) ? bi : bj;
    int colbase = (ntile & 1) * 128;
#pragma unroll
    for (int mi = 0; mi < 2; mi++) {
        int mrow0 = m0 + m_base + mi * 16 + (lane >> 2);
#pragma unroll
        for (int nb = 0; nb < 4; nb++) {
            int n = n_base + nb * 8 + 2 * (lane & 3);
            float b0 = bias[colbase + n], b1 = bias[colbase + n + 1];
            if (mrow0 < NN) {
                float2 v = make_float2(acc[mi][nb][0] + b0, acc[mi][nb][1] + b1);
                *(float2*)(P + (size_t)mrow0 * 256 + colbase + n) = v;
            }
            if (mrow0 + 8 < NN) {
                float2 v = make_float2(acc[mi][nb][2] + b0, acc[mi][nb][3] + b1);
                *(float2*)(P + (size_t)(mrow0 + 8) * 256 + colbase + n) = v;
            }
        }
    }
}

// ---------------- edge logits: one warp per edge ----------------
__global__ __launch_bounds__(256) void edge_logits_kernel(
    const int* __restrict__ senders, const int* __restrict__ receivers,
    const float* __restrict__ a_w, const float* __restrict__ a_b)
{
    int warp = (blockIdx.x * blockDim.x + threadIdx.x) >> 5;
    int lane = threadIdx.x & 31;
    if (warp >= NE) return;

    int s = senders[warp];
    int r = receivers[warp];
    float aw = a_w[lane];
    float ab = a_b[0];
    const float* pi = g_Pi + (size_t)s * 256;
    const float* pj = g_Pj + (size_t)r * 256;

    float p[NH];
#pragma unroll
    for (int h = 0; h < NH; h++) {
        float x = pi[h * 32 + lane] + pj[h * 32 + lane];
        float sp = fmaxf(x, 0.0f) + log1pf(__expf(-fabsf(x)));
        float m = x * tanhf(sp);
        p[h] = m * aw;
    }
#pragma unroll
    for (int off = 16; off > 0; off >>= 1)
#pragma unroll
        for (int h = 0; h < NH; h++)
            p[h] += __shfl_xor_sync(0xffffffffu, p[h], off);

    if (lane == 0) {
#pragma unroll
        for (int h = 0; h < NH; h++) {
            float v = p[h] + ab;
            g_logits[(size_t)warp * NH + h] = v;
            atomicMax(&g_nmax[(size_t)r * NH + h], fenc(v));
        }
    }
}

// ---------------- exp + denom ----------------
__global__ __launch_bounds__(256) void edge_exp_kernel(const int* __restrict__ receivers)
{
    int i = blockIdx.x * blockDim.x + threadIdx.x;
    if (i >= NE * NH) return;
    int e = i >> 3;
    int h = i & 7;
    int r = receivers[e];
    float m = fdec(g_nmax[(size_t)r * NH + h]);
    float v = __expf(g_logits[i] - m);
    g_wun[i] = v;
    atomicAdd(&g_denom[(size_t)r * NH + h], v);
}

// ---------------- weighted aggregation ----------------
__global__ __launch_bounds__(256) void edge_agg_kernel(
    const int* __restrict__ senders, const int* __restrict__ receivers,
    float* __restrict__ out)
{
    int warp = (blockIdx.x * blockDim.x + threadIdx.x) >> 5;
    int lane = threadIdx.x & 31;
    if (warp >= NE) return;

    int s = senders[warp];
    int r = receivers[warp];
    const float* pi = g_Pi + (size_t)s * 256;
    float* o = out + (size_t)r * 256;

    float tmp = 0.0f;
    if (lane < NH)
        tmp = g_wun[(size_t)warp * NH + lane] / g_denom[(size_t)r * NH + lane];
    float w[NH];
#pragma unroll
    for (int h = 0; h < NH; h++)
        w[h] = __shfl_sync(0xffffffffu, tmp, h);

#pragma unroll
    for (int h = 0; h < NH; h++)
        atomicAdd(&o[h * 32 + lane], pi[h * 32 + lane] * w[h]);
}

// ---------------- launch ----------------
extern "C" void kernel_launch(void* const* d_in, const int* in_sizes, int n_in,
                              void* d_out, int out_size)
{
    const float* nodes     = (const float*)d_in[0];
    const int*   senders   = (const int*)d_in[1];
    const int*   receivers = (const int*)d_in[2];
    const float* Wi        = (const float*)d_in[3];
    const float* bi        = (const float*)d_in[4];
    const float* Wj        = (const float*)d_in[5];
    const float* bj        = (const float*)d_in[6];
    const float* a_w       = (const float*)d_in[7];
    const float* a_b       = (const float*)d_in[8];
    float* out = (float*)d_out;

    static bool attr_set = false;
    if (!attr_set) {
        cudaFuncSetAttribute(gemm_mma, cudaFuncAttributeMaxDynamicSharedMemorySize, 66560);
        attr_set = true;
    }

    init_kernel<<<512, 256>>>(out);

    presplit_nodes<<<(NN * DIN / 8 + 255) / 256, 256>>>(nodes);
    presplit_W<<<(512 * 256 + 255) / 256, 256>>>(Wi, Wj);

    dim3 gg((NN + 127) / 128, 4);
    gemm_mma<<<gg, 512, 66560>>>(bi, bj);

    edge_logits_kernel<<<(NE * 32) / 256, 256>>>(senders, receivers, a_w, a_b);

    edge_exp_kernel<<<(NE * NH + 255) / 256, 256>>>(receivers);

    edge_agg_kernel<<<(NE * 32) / 256, 256>>>(senders, receivers, out);
}

// round 4
// speedup vs baseline: 1.4144x; 1.1318x over previous
#include <cuda_runtime.h>
#include <cuda_bf16.h>
#include <cstdint>
#include <math.h>

#define NN 50000
#define NE 400000
#define DIN 256
#define EMB 256
#define NH 8
#define HD 32

// ---------------- scratch (device globals; no runtime alloc) ----------------
__device__ __align__(16) float    g_Pi[(size_t)NN * EMB];
__device__ __align__(16) float    g_Pj[(size_t)NN * EMB];
__device__ __align__(16) float    g_logits[(size_t)NE * NH];   // perm-order
__device__ __align__(16) float    g_wun[(size_t)NE * NH];      // perm-order, unnormalized
__device__ __align__(16) float    g_denom[(size_t)NN * NH];

// CSR
__device__ int g_cnt[NN];
__device__ int g_off[NN + 1];
__device__ int g_cursor[NN];
__device__ int g_psend[NE];    // sender of perm-ordered edge
__device__ int g_precv[NE];    // receiver of perm-ordered edge

// split-bf16 operands for tensor-core GEMM
__device__ __align__(16) __nv_bfloat16 g_Ahi[(size_t)NN * DIN];
__device__ __align__(16) __nv_bfloat16 g_Alo[(size_t)NN * DIN];
__device__ __align__(16) __nv_bfloat16 g_Bhi[(size_t)512 * DIN];  // [n_global][k]
__device__ __align__(16) __nv_bfloat16 g_Blo[(size_t)512 * DIN];

// ---------------- helpers ----------------
__device__ __forceinline__ uint32_t smem_u32(const void* p) {
    uint32_t a;
    asm("{ .reg .u64 t; cvta.to.shared.u64 t, %1; cvt.u32.u64 %0, t; }" : "=r"(a) : "l"(p));
    return a;
}
__device__ __forceinline__ uint32_t sw128(uint32_t off) { return off ^ ((off >> 3) & 0x70); }

__device__ __forceinline__ void ldsm_x4(uint32_t* r, uint32_t addr) {
    asm volatile("ldmatrix.sync.aligned.m8n8.x4.shared.b16 {%0,%1,%2,%3}, [%4];"
                 : "=r"(r[0]), "=r"(r[1]), "=r"(r[2]), "=r"(r[3]) : "r"(addr));
}
__device__ __forceinline__ void mma16816(float* c, const uint32_t* a, const uint32_t* b) {
    asm volatile("mma.sync.aligned.m16n8k16.row.col.f32.bf16.bf16.f32 "
                 "{%0,%1,%2,%3}, {%4,%5,%6,%7}, {%8,%9}, {%0,%1,%2,%3};"
                 : "+f"(c[0]), "+f"(c[1]), "+f"(c[2]), "+f"(c[3])
                 : "r"(a[0]), "r"(a[1]), "r"(a[2]), "r"(a[3]), "r"(b[0]), "r"(b[1]));
}
__device__ __forceinline__ void cp_async16(uint32_t dst, const void* src) {
    asm volatile("cp.async.cg.shared.global [%0], [%1], 16;" :: "r"(dst), "l"(src));
}
#define CP_COMMIT() asm volatile("cp.async.commit_group;" ::: "memory")
#define CP_WAIT(n)  asm volatile("cp.async.wait_group %0;" :: "n"(n) : "memory")

// ---------------- init: zero CSR counters ----------------
__global__ void init_kernel() {
    int i = blockIdx.x * blockDim.x + threadIdx.x;
    if (i < NN) g_cnt[i] = 0;
}

// ---------------- pre-split nodes into bf16 hi/lo ----------------
__global__ __launch_bounds__(256) void presplit_nodes(const float* __restrict__ nodes) {
    size_t i = (size_t)blockIdx.x * blockDim.x + threadIdx.x;   // unit of 8 floats
    size_t total = (size_t)NN * DIN / 8;
    if (i >= total) return;
    const float4* src = (const float4*)nodes + i * 2;
    float4 v0 = src[0], v1 = src[1];
    float f[8] = {v0.x, v0.y, v0.z, v0.w, v1.x, v1.y, v1.z, v1.w};
    alignas(16) __nv_bfloat16 h[8];
    alignas(16) __nv_bfloat16 l[8];
#pragma unroll
    for (int j = 0; j < 8; j++) {
        h[j] = __float2bfloat16(f[j]);
        l[j] = __float2bfloat16(f[j] - __bfloat162float(h[j]));
    }
    *(uint4*)(g_Ahi + i * 8) = *(uint4*)h;
    *(uint4*)(g_Alo + i * 8) = *(uint4*)l;
}

// ---------------- pre-split + transpose W into [n][k] bf16 hi/lo ----------------
__global__ __launch_bounds__(256) void presplit_W(const float* __restrict__ Wi,
                                                  const float* __restrict__ Wj) {
    int idx = blockIdx.x * blockDim.x + threadIdx.x;
    if (idx >= 512 * 256) return;
    int n = idx >> 8, k = idx & 255;
    const float* W = (n < 256) ? Wi : Wj;
    int col = n & 255;
    float x = W[(size_t)k * 256 + col];
    __nv_bfloat16 h = __float2bfloat16(x);
    __nv_bfloat16 l = __float2bfloat16(x - __bfloat162float(h));
    g_Bhi[(size_t)n * 256 + k] = h;
    g_Blo[(size_t)n * 256 + k] = l;
}

// ---------------- tensor-core projection GEMM, 2-stage cp.async pipeline ----
// grid = (4 ntiles, 391 mtiles): CTAs sharing an A tile run concurrently (L2 reuse)
__global__ __launch_bounds__(512) void gemm_mma(const float* __restrict__ bi,
                                                const float* __restrict__ bj) {
    extern __shared__ char dsm[];
    uint32_t base = (smem_u32(dsm) + 1023) & ~1023u;

    int tid = threadIdx.x, wid = tid >> 5, lane = tid & 31;
    int warp_m = wid & 3, warp_n = wid >> 2;
    int m_base = warp_m * 32, n_base = warp_n * 32;
    int ntile = blockIdx.x;
    int m0 = blockIdx.y * 128;
    size_t brow0 = (size_t)ntile * 128 * 256;

    float acc[2][4][4];
#pragma unroll
    for (int i = 0; i < 2; i++)
#pragma unroll
        for (int j = 0; j < 4; j++)
#pragma unroll
            for (int q = 0; q < 4; q++) acc[i][j][q] = 0.0f;

#define LOAD_STAGE(sbuf, kc_) do {                                         \
    uint32_t sAh_ = (sbuf), sAl_ = (sbuf) + 16384,                          \
             sBh_ = (sbuf) + 32768, sBl_ = (sbuf) + 49152;                  \
    int k0_ = (kc_) * 64;                                                   \
    _Pragma("unroll")                                                       \
    for (int u = tid; u < 1024; u += 512) {                                 \
        int r_ = u >> 3, g_ = u & 7;                                        \
        uint32_t off_ = sw128((uint32_t)(r_ * 128 + g_ * 16));              \
        int row_ = m0 + r_; if (row_ > NN - 1) row_ = NN - 1;               \
        size_t sa_ = (size_t)row_ * 256 + k0_ + g_ * 8;                     \
        cp_async16(sAh_ + off_, g_Ahi + sa_);                               \
        cp_async16(sAl_ + off_, g_Alo + sa_);                               \
        size_t sb_ = brow0 + (size_t)r_ * 256 + k0_ + g_ * 8;               \
        cp_async16(sBh_ + off_, g_Bhi + sb_);                               \
        cp_async16(sBl_ + off_, g_Blo + sb_);                               \
    }                                                                       \
} while (0)

    LOAD_STAGE(base, 0);
    CP_COMMIT();

    for (int kc = 0; kc < 4; kc++) {
        uint32_t cur = base + (uint32_t)(kc & 1) * 65536;
        if (kc < 3) {
            LOAD_STAGE(base + (uint32_t)((kc + 1) & 1) * 65536, kc + 1);
            CP_COMMIT();
            CP_WAIT(1);
        } else {
            CP_WAIT(0);
        }
        __syncthreads();

        uint32_t sAh = cur, sAl = cur + 16384, sBh = cur + 32768, sBl = cur + 49152;
#pragma unroll
        for (int ks = 0; ks < 4; ks++) {
            uint32_t ah[2][4], al[2][4];
#pragma unroll
            for (int mi = 0; mi < 2; mi++) {
                uint32_t off = sw128((uint32_t)((m_base + mi * 16 + (lane & 15)) * 128 +
                                                ks * 32 + (lane >> 4) * 16));
                ldsm_x4(ah[mi], sAh + off);
                ldsm_x4(al[mi], sAl + off);
            }
            uint32_t bh[8], bl[8];
#pragma unroll
            for (int np = 0; np < 2; np++) {
                int g = lane >> 3;
                int nrow = n_base + np * 16 + (lane & 7) + ((g & 2) ? 8 : 0);
                uint32_t off = sw128((uint32_t)(nrow * 128 + ks * 32 + (g & 1) * 16));
                ldsm_x4(&bh[np * 4], sBh + off);
                ldsm_x4(&bl[np * 4], sBl + off);
            }
#pragma unroll
            for (int mi = 0; mi < 2; mi++)
#pragma unroll
                for (int nb = 0; nb < 4; nb++) {
                    const int bo = (nb >> 1) * 4 + (nb & 1) * 2;
                    mma16816(acc[mi][nb], ah[mi], &bh[bo]);
                    mma16816(acc[mi][nb], ah[mi], &bl[bo]);
                    mma16816(acc[mi][nb], al[mi], &bh[bo]);
                }
        }
        __syncthreads();
    }

    float* P = (ntile < 2) ? g_Pi : g_Pj;
    const float* bias = (ntile < 2) ? bi : bj;
    int colbase = (ntile & 1) * 128;
#pragma unroll
    for (int mi = 0; mi < 2; mi++) {
        int mrow0 = m0 + m_base + mi * 16 + (lane >> 2);
#pragma unroll
        for (int nb = 0; nb < 4; nb++) {
            int n = n_base + nb * 8 + 2 * (lane & 3);
            float b0 = bias[colbase + n], b1 = bias[colbase + n + 1];
            if (mrow0 < NN) {
                float2 v = make_float2(acc[mi][nb][0] + b0, acc[mi][nb][1] + b1);
                *(float2*)(P + (size_t)mrow0 * 256 + colbase + n) = v;
            }
            if (mrow0 + 8 < NN) {
                float2 v = make_float2(acc[mi][nb][2] + b0, acc[mi][nb][3] + b1);
                *(float2*)(P + (size_t)(mrow0 + 8) * 256 + colbase + n) = v;
            }
        }
    }
#undef LOAD_STAGE
}

// ---------------- CSR build ----------------
__global__ void hist_kernel(const int* __restrict__ receivers) {
    int e = blockIdx.x * blockDim.x + threadIdx.x;
    if (e < NE) atomicAdd(&g_cnt[receivers[e]], 1);
}

// single-block exclusive scan of g_cnt -> g_off, g_cursor
__global__ __launch_bounds__(1024) void scan_kernel() {
    __shared__ int sh[1024];
    const int CH = 49;   // 1024*49 >= 50000
    int tid = threadIdx.x;
    int base = tid * CH;
    int s = 0;
    for (int i = 0; i < CH; i++) {
        int idx = base + i;
        if (idx < NN) s += g_cnt[idx];
    }
    sh[tid] = s;
    __syncthreads();
    int incl = s;
    for (int d = 1; d < 1024; d <<= 1) {
        int t = (tid >= d) ? sh[tid - d] : 0;
        __syncthreads();
        incl += t;
        sh[tid] = incl;
        __syncthreads();
    }
    int run = incl - s;   // exclusive prefix of this thread's chunk
    for (int i = 0; i < CH; i++) {
        int idx = base + i;
        if (idx < NN) {
            int c = g_cnt[idx];
            g_off[idx] = run;
            g_cursor[idx] = run;
            run += c;
        }
    }
    if (tid == 0) g_off[NN] = NE;
}

__global__ void scatter_kernel(const int* __restrict__ senders,
                               const int* __restrict__ receivers) {
    int e = blockIdx.x * blockDim.x + threadIdx.x;
    if (e >= NE) return;
    int r = receivers[e];
    int pos = atomicAdd(&g_cursor[r], 1);
    g_psend[pos] = senders[e];
    g_precv[pos] = r;
}

// ---------------- edge logits (perm order): one warp per edge ----------------
__global__ __launch_bounds__(256) void edge_logits_kernel(
    const float* __restrict__ a_w, const float* __restrict__ a_b)
{
    int j = (blockIdx.x * blockDim.x + threadIdx.x) >> 5;
    int lane = threadIdx.x & 31;
    if (j >= NE) return;

    int s = g_psend[j];
    int r = g_precv[j];
    float aw = a_w[lane];
    float ab = a_b[0];
    const float* pi = g_Pi + (size_t)s * 256;
    const float* pj = g_Pj + (size_t)r * 256;

    float p[NH];
#pragma unroll
    for (int h = 0; h < NH; h++) {
        float x = pi[h * 32 + lane] + pj[h * 32 + lane];
        float sp = fmaxf(x, 0.0f) + log1pf(__expf(-fabsf(x)));
        float m = x * tanhf(sp);
        p[h] = m * aw;
    }
#pragma unroll
    for (int off = 16; off > 0; off >>= 1)
#pragma unroll
        for (int h = 0; h < NH; h++)
            p[h] += __shfl_xor_sync(0xffffffffu, p[h], off);

    if (lane == 0) {
        float* lp = g_logits + (size_t)j * 8;
        *(float4*)(lp)     = make_float4(p[0] + ab, p[1] + ab, p[2] + ab, p[3] + ab);
        *(float4*)(lp + 4) = make_float4(p[4] + ab, p[5] + ab, p[6] + ab, p[7] + ab);
    }
}

// ---------------- segment softmax: one warp per receiver, no atomics ----------
__global__ __launch_bounds__(256) void softmax_kernel() {
    int r = (blockIdx.x * blockDim.x + threadIdx.x) >> 5;
    int lane = threadIdx.x & 31;
    if (r >= NN) return;
    int lo = g_off[r], hi = g_off[r + 1];
    int deg = hi - lo;
    if (deg == 0) {
        if (lane < 8) g_denom[(size_t)r * 8 + lane] = 1.0f;
        return;
    }
    float mx[8];
#pragma unroll
    for (int h = 0; h < 8; h++) mx[h] = -INFINITY;
    for (int j2 = lane; j2 < deg; j2 += 32) {
        const float* lp = g_logits + (size_t)(lo + j2) * 8;
#pragma unroll
        for (int h = 0; h < 8; h++) mx[h] = fmaxf(mx[h], lp[h]);
    }
#pragma unroll
    for (int off = 16; off > 0; off >>= 1)
#pragma unroll
        for (int h = 0; h < 8; h++)
            mx[h] = fmaxf(mx[h], __shfl_xor_sync(0xffffffffu, mx[h], off));

    float sm[8];
#pragma unroll
    for (int h = 0; h < 8; h++) sm[h] = 0.0f;
    for (int j2 = lane; j2 < deg; j2 += 32) {
        const float* lp = g_logits + (size_t)(lo + j2) * 8;
        float* wp = g_wun + (size_t)(lo + j2) * 8;
#pragma unroll
        for (int h = 0; h < 8; h++) {
            float v = __expf(lp[h] - mx[h]);
            wp[h] = v;
            sm[h] += v;
        }
    }
#pragma unroll
    for (int off = 16; off > 0; off >>= 1)
#pragma unroll
        for (int h = 0; h < 8; h++)
            sm[h] += __shfl_xor_sync(0xffffffffu, sm[h], off);

    if (lane < 8) g_denom[(size_t)r * 8 + lane] = sm[lane];
}

// ---------------- aggregation: one warp per receiver, register accum ---------
__global__ __launch_bounds__(256) void agg_kernel(float* __restrict__ out) {
    int r = (blockIdx.x * blockDim.x + threadIdx.x) >> 5;
    int lane = threadIdx.x & 31;
    if (r >= NN) return;
    int lo = g_off[r], hi = g_off[r + 1];
    int deg = hi - lo;

    float acc[8];
#pragma unroll
    for (int h = 0; h < 8; h++) acc[h] = 0.0f;

    for (int j2 = 0; j2 < deg; j2++) {
        int idx = lo + j2;
        int s = g_psend[idx];
        float t = (lane < 8) ? g_wun[(size_t)idx * 8 + lane] : 0.0f;
        const float* pi = g_Pi + (size_t)s * 256;
#pragma unroll
        for (int h = 0; h < 8; h++) {
            float w = __shfl_sync(0xffffffffu, t, h);
            acc[h] = fmaf(pi[h * 32 + lane], w, acc[h]);
        }
    }
    float td = (lane < 8) ? 1.0f / g_denom[(size_t)r * 8 + lane] : 0.0f;
    float* o = out + (size_t)r * 256;
#pragma unroll
    for (int h = 0; h < 8; h++) {
        float rd = __shfl_sync(0xffffffffu, td, h);
        o[h * 32 + lane] = acc[h] * rd;
    }
}

// ---------------- launch ----------------
extern "C" void kernel_launch(void* const* d_in, const int* in_sizes, int n_in,
                              void* d_out, int out_size)
{
    const float* nodes     = (const float*)d_in[0];
    const int*   senders   = (const int*)d_in[1];
    const int*   receivers = (const int*)d_in[2];
    const float* Wi        = (const float*)d_in[3];
    const float* bi        = (const float*)d_in[4];
    const float* Wj        = (const float*)d_in[5];
    const float* bj        = (const float*)d_in[6];
    const float* a_w       = (const float*)d_in[7];
    const float* a_b       = (const float*)d_in[8];
    float* out = (float*)d_out;

    static bool attr_set = false;
    if (!attr_set) {
        cudaFuncSetAttribute(gemm_mma, cudaFuncAttributeMaxDynamicSharedMemorySize, 132096);
        attr_set = true;
    }

    init_kernel<<<(NN + 255) / 256, 256>>>();

    presplit_nodes<<<(NN * DIN / 8 + 255) / 256, 256>>>(nodes);
    presplit_W<<<(512 * 256 + 255) / 256, 256>>>(Wi, Wj);

    dim3 gg(4, (NN + 127) / 128);
    gemm_mma<<<gg, 512, 132096>>>(bi, bj);

    hist_kernel<<<(NE + 255) / 256, 256>>>(receivers);
    scan_kernel<<<1, 1024>>>();
    scatter_kernel<<<(NE + 255) / 256, 256>>>(senders, receivers);

    edge_logits_kernel<<<(NE * 32) / 256, 256>>>(a_w, a_b);

    softmax_kernel<<<(NN * 32 + 255) / 256, 256>>>();

    agg_kernel<<<(NN * 32 + 255) / 256, 256>>>(out);
}

// round 5
// speedup vs baseline: 2.0513x; 1.4503x over previous
#include <cuda_runtime.h>
#include <cuda_bf16.h>
#include <cstdint>
#include <math.h>

#define NN 50000
#define NE 400000
#define DIN 256
#define EMB 256
#define NH 8
#define HD 32

// ---------------- scratch (device globals; no runtime alloc) ----------------
__device__ __align__(16) float    g_Pi[(size_t)NN * EMB];
__device__ __align__(16) float    g_Pj[(size_t)NN * EMB];
__device__ __align__(16) float    g_spill[(size_t)NE * NH];    // rare deg>32 spill

// CSR
__device__ int g_cnt[NN];
__device__ int g_off[NN + 1];
__device__ int g_cursor[NN];
__device__ int g_psend[NE];    // sender of perm-ordered edge

// split-bf16 operands for tensor-core GEMM
__device__ __align__(16) __nv_bfloat16 g_Ahi[(size_t)NN * DIN];
__device__ __align__(16) __nv_bfloat16 g_Alo[(size_t)NN * DIN];
__device__ __align__(16) __nv_bfloat16 g_Bhi[(size_t)512 * DIN];  // [n_global][k]
__device__ __align__(16) __nv_bfloat16 g_Blo[(size_t)512 * DIN];

// ---------------- helpers ----------------
__device__ __forceinline__ uint32_t smem_u32(const void* p) {
    uint32_t a;
    asm("{ .reg .u64 t; cvta.to.shared.u64 t, %1; cvt.u32.u64 %0, t; }" : "=r"(a) : "l"(p));
    return a;
}
__device__ __forceinline__ uint32_t sw128(uint32_t off) { return off ^ ((off >> 3) & 0x70); }

__device__ __forceinline__ void ldsm_x4(uint32_t* r, uint32_t addr) {
    asm volatile("ldmatrix.sync.aligned.m8n8.x4.shared.b16 {%0,%1,%2,%3}, [%4];"
                 : "=r"(r[0]), "=r"(r[1]), "=r"(r[2]), "=r"(r[3]) : "r"(addr));
}
__device__ __forceinline__ void mma16816(float* c, const uint32_t* a, const uint32_t* b) {
    asm volatile("mma.sync.aligned.m16n8k16.row.col.f32.bf16.bf16.f32 "
                 "{%0,%1,%2,%3}, {%4,%5,%6,%7}, {%8,%9}, {%0,%1,%2,%3};"
                 : "+f"(c[0]), "+f"(c[1]), "+f"(c[2]), "+f"(c[3])
                 : "r"(a[0]), "r"(a[1]), "r"(a[2]), "r"(a[3]), "r"(b[0]), "r"(b[1]));
}
__device__ __forceinline__ void cp_async16(uint32_t dst, const void* src) {
    asm volatile("cp.async.cg.shared.global [%0], [%1], 16;" :: "r"(dst), "l"(src));
}
#define CP_COMMIT() asm volatile("cp.async.commit_group;" ::: "memory")
#define CP_WAIT(n)  asm volatile("cp.async.wait_group %0;" :: "n"(n) : "memory")

// mish(x) = x * tanh(softplus(x)) = x * (t^2 + 2t) / (t^2 + 2t + 2),  t = e^x
__device__ __forceinline__ float mish1(float x) {
    if (x > 20.0f) return x;
    float t = __expf(x);
    float u = fmaf(t, t, t + t);
    return x * __fdividef(u, u + 2.0f);
}

// ---------------- init: zero CSR counters ----------------
__global__ void init_kernel() {
    int i = blockIdx.x * blockDim.x + threadIdx.x;
    if (i < NN) g_cnt[i] = 0;
}

// ---------------- pre-split nodes into bf16 hi/lo ----------------
__global__ __launch_bounds__(256) void presplit_nodes(const float* __restrict__ nodes) {
    size_t i = (size_t)blockIdx.x * blockDim.x + threadIdx.x;   // unit of 8 floats
    size_t total = (size_t)NN * DIN / 8;
    if (i >= total) return;
    const float4* src = (const float4*)nodes + i * 2;
    float4 v0 = src[0], v1 = src[1];
    float f[8] = {v0.x, v0.y, v0.z, v0.w, v1.x, v1.y, v1.z, v1.w};
    alignas(16) __nv_bfloat16 h[8];
    alignas(16) __nv_bfloat16 l[8];
#pragma unroll
    for (int j = 0; j < 8; j++) {
        h[j] = __float2bfloat16(f[j]);
        l[j] = __float2bfloat16(f[j] - __bfloat162float(h[j]));
    }
    *(uint4*)(g_Ahi + i * 8) = *(uint4*)h;
    *(uint4*)(g_Alo + i * 8) = *(uint4*)l;
}

// ---------------- pre-split + transpose W into [n][k] bf16 hi/lo ----------------
__global__ __launch_bounds__(256) void presplit_W(const float* __restrict__ Wi,
                                                  const float* __restrict__ Wj) {
    int idx = blockIdx.x * blockDim.x + threadIdx.x;
    if (idx >= 512 * 256) return;
    int n = idx >> 8, k = idx & 255;
    const float* W = (n < 256) ? Wi : Wj;
    int col = n & 255;
    float x = W[(size_t)k * 256 + col];
    __nv_bfloat16 h = __float2bfloat16(x);
    __nv_bfloat16 l = __float2bfloat16(x - __bfloat162float(h));
    g_Bhi[(size_t)n * 256 + k] = h;
    g_Blo[(size_t)n * 256 + k] = l;
}

// ---------------- tensor-core projection GEMM, 2-stage cp.async pipeline ----
__global__ __launch_bounds__(512) void gemm_mma(const float* __restrict__ bi,
                                                const float* __restrict__ bj) {
    extern __shared__ char dsm[];
    uint32_t base = (smem_u32(dsm) + 1023) & ~1023u;

    int tid = threadIdx.x, wid = tid >> 5, lane = tid & 31;
    int warp_m = wid & 3, warp_n = wid >> 2;
    int m_base = warp_m * 32, n_base = warp_n * 32;
    int ntile = blockIdx.x;
    int m0 = blockIdx.y * 128;
    size_t brow0 = (size_t)ntile * 128 * 256;

    float acc[2][4][4];
#pragma unroll
    for (int i = 0; i < 2; i++)
#pragma unroll
        for (int j = 0; j < 4; j++)
#pragma unroll
            for (int q = 0; q < 4; q++) acc[i][j][q] = 0.0f;

#define LOAD_STAGE(sbuf, kc_) do {                                         \
    uint32_t sAh_ = (sbuf), sAl_ = (sbuf) + 16384,                          \
             sBh_ = (sbuf) + 32768, sBl_ = (sbuf) + 49152;                  \
    int k0_ = (kc_) * 64;                                                   \
    _Pragma("unroll")                                                       \
    for (int u = tid; u < 1024; u += 512) {                                 \
        int r_ = u >> 3, g_ = u & 7;                                        \
        uint32_t off_ = sw128((uint32_t)(r_ * 128 + g_ * 16));              \
        int row_ = m0 + r_; if (row_ > NN - 1) row_ = NN - 1;               \
        size_t sa_ = (size_t)row_ * 256 + k0_ + g_ * 8;                     \
        cp_async16(sAh_ + off_, g_Ahi + sa_);                               \
        cp_async16(sAl_ + off_, g_Alo + sa_);                               \
        size_t sb_ = brow0 + (size_t)r_ * 256 + k0_ + g_ * 8;               \
        cp_async16(sBh_ + off_, g_Bhi + sb_);                               \
        cp_async16(sBl_ + off_, g_Blo + sb_);                               \
    }                                                                       \
} while (0)

    LOAD_STAGE(base, 0);
    CP_COMMIT();

    for (int kc = 0; kc < 4; kc++) {
        uint32_t cur = base + (uint32_t)(kc & 1) * 65536;
        if (kc < 3) {
            LOAD_STAGE(base + (uint32_t)((kc + 1) & 1) * 65536, kc + 1);
            CP_COMMIT();
            CP_WAIT(1);
        } else {
            CP_WAIT(0);
        }
        __syncthreads();

        uint32_t sAh = cur, sAl = cur + 16384, sBh = cur + 32768, sBl = cur + 49152;
#pragma unroll
        for (int ks = 0; ks < 4; ks++) {
            uint32_t ah[2][4], al[2][4];
#pragma unroll
            for (int mi = 0; mi < 2; mi++) {
                uint32_t off = sw128((uint32_t)((m_base + mi * 16 + (lane & 15)) * 128 +
                                                ks * 32 + (lane >> 4) * 16));
                ldsm_x4(ah[mi], sAh + off);
                ldsm_x4(al[mi], sAl + off);
            }
            uint32_t bh[8], bl[8];
#pragma unroll
            for (int np = 0; np < 2; np++) {
                int g = lane >> 3;
                int nrow = n_base + np * 16 + (lane & 7) + ((g & 2) ? 8 : 0);
                uint32_t off = sw128((uint32_t)(nrow * 128 + ks * 32 + (g & 1) * 16));
                ldsm_x4(&bh[np * 4], sBh + off);
                ldsm_x4(&bl[np * 4], sBl + off);
            }
#pragma unroll
            for (int mi = 0; mi < 2; mi++)
#pragma unroll
                for (int nb = 0; nb < 4; nb++) {
                    const int bo = (nb >> 1) * 4 + (nb & 1) * 2;
                    mma16816(acc[mi][nb], ah[mi], &bh[bo]);
                    mma16816(acc[mi][nb], ah[mi], &bl[bo]);
                    mma16816(acc[mi][nb], al[mi], &bh[bo]);
                }
        }
        __syncthreads();
    }

    float* P = (ntile < 2) ? g_Pi : g_Pj;
    const float* bias = (ntile < 2) ? bi : bj;
    int colbase = (ntile & 1) * 128;
#pragma unroll
    for (int mi = 0; mi < 2; mi++) {
        int mrow0 = m0 + m_base + mi * 16 + (lane >> 2);
#pragma unroll
        for (int nb = 0; nb < 4; nb++) {
            int n = n_base + nb * 8 + 2 * (lane & 3);
            float b0 = bias[colbase + n], b1 = bias[colbase + n + 1];
            if (mrow0 < NN) {
                float2 v = make_float2(acc[mi][nb][0] + b0, acc[mi][nb][1] + b1);
                *(float2*)(P + (size_t)mrow0 * 256 + colbase + n) = v;
            }
            if (mrow0 + 8 < NN) {
                float2 v = make_float2(acc[mi][nb][2] + b0, acc[mi][nb][3] + b1);
                *(float2*)(P + (size_t)(mrow0 + 8) * 256 + colbase + n) = v;
            }
        }
    }
#undef LOAD_STAGE
}

// ---------------- CSR build ----------------
__global__ void hist_kernel(const int* __restrict__ receivers) {
    int e = blockIdx.x * blockDim.x + threadIdx.x;
    if (e < NE) atomicAdd(&g_cnt[receivers[e]], 1);
}

__global__ __launch_bounds__(1024) void scan_kernel() {
    __shared__ int sh[1024];
    const int CH = 49;
    int tid = threadIdx.x;
    int base = tid * CH;
    int s = 0;
    for (int i = 0; i < CH; i++) {
        int idx = base + i;
        if (idx < NN) s += g_cnt[idx];
    }
    sh[tid] = s;
    __syncthreads();
    int incl = s;
    for (int d = 1; d < 1024; d <<= 1) {
        int t = (tid >= d) ? sh[tid - d] : 0;
        __syncthreads();
        incl += t;
        sh[tid] = incl;
        __syncthreads();
    }
    int run = incl - s;
    for (int i = 0; i < CH; i++) {
        int idx = base + i;
        if (idx < NN) {
            int c = g_cnt[idx];
            g_off[idx] = run;
            g_cursor[idx] = run;
            run += c;
        }
    }
    if (tid == 0) g_off[NN] = NE;
}

__global__ void scatter_kernel(const int* __restrict__ senders,
                               const int* __restrict__ receivers) {
    int e = blockIdx.x * blockDim.x + threadIdx.x;
    if (e >= NE) return;
    int r = receivers[e];
    int pos = atomicAdd(&g_cursor[r], 1);
    g_psend[pos] = senders[e];
}

// ---------------- fused edge phase: warp per receiver --------------------
// lane owns elements c*128 + lane*4 .. +3 (c=0,1): head = c*4 + lane/8,
// k within head = (lane&7)*4 + q.
__global__ __launch_bounds__(256) void fused_edge_kernel(
    const float* __restrict__ a_w, const float* __restrict__ a_b,
    float* __restrict__ out)
{
    __shared__ float s_w[8][32 * NH];
    int wib = threadIdx.x >> 5;
    int lane = threadIdx.x & 31;
    int r = blockIdx.x * 8 + wib;
    if (r >= NN) return;
    int lo = g_off[r];
    int deg = g_off[r + 1] - lo;

    float4 acc0 = make_float4(0.f, 0.f, 0.f, 0.f);
    float4 acc1 = make_float4(0.f, 0.f, 0.f, 0.f);

    if (deg > 0) {
        float ab = a_b[0];
        float4 awv = *(const float4*)(a_w + (lane & 7) * 4);
        const float4* pj4 = (const float4*)(g_Pj + (size_t)r * 256);
        float4 pjv0 = pj4[lane];
        float4 pjv1 = pj4[32 + lane];
        float* wbuf = (deg <= 32) ? s_w[wib] : (g_spill + (size_t)lo * NH);

        int hgrp = lane >> 3;               // 0..3
        bool writer = (lane & 7) == 0;
        const int* ps = g_psend + lo;

        // ---- pass 1: logits ----
#pragma unroll 2
        for (int j = 0; j < deg; j++) {
            int s = ps[j];
            const float4* pi4 = (const float4*)(g_Pi + (size_t)s * 256);
            float4 v0 = pi4[lane];
            float4 v1 = pi4[32 + lane];
            float p0 = mish1(v0.x + pjv0.x) * awv.x;
            p0 = fmaf(mish1(v0.y + pjv0.y), awv.y, p0);
            p0 = fmaf(mish1(v0.z + pjv0.z), awv.z, p0);
            p0 = fmaf(mish1(v0.w + pjv0.w), awv.w, p0);
            float p1 = mish1(v1.x + pjv1.x) * awv.x;
            p1 = fmaf(mish1(v1.y + pjv1.y), awv.y, p1);
            p1 = fmaf(mish1(v1.z + pjv1.z), awv.z, p1);
            p1 = fmaf(mish1(v1.w + pjv1.w), awv.w, p1);
#pragma unroll
            for (int o = 4; o > 0; o >>= 1) {
                p0 += __shfl_xor_sync(0xffffffffu, p0, o);
                p1 += __shfl_xor_sync(0xffffffffu, p1, o);
            }
            if (writer) {
                wbuf[j * NH + hgrp] = p0 + ab;
                wbuf[j * NH + 4 + hgrp] = p1 + ab;
            }
        }
        __syncwarp();

        // ---- softmax over this receiver's edges ----
        {
            int h = lane >> 2;       // head 0..7
            int e0 = lane & 3;       // edge stripe
            float mx = -INFINITY;
            for (int j = e0; j < deg; j += 4) mx = fmaxf(mx, wbuf[j * NH + h]);
            mx = fmaxf(mx, __shfl_xor_sync(0xffffffffu, mx, 1));
            mx = fmaxf(mx, __shfl_xor_sync(0xffffffffu, mx, 2));
            float sm = 0.0f;
            for (int j = e0; j < deg; j += 4) {
                float e = __expf(wbuf[j * NH + h] - mx);
                wbuf[j * NH + h] = e;
                sm += e;
            }
            sm += __shfl_xor_sync(0xffffffffu, sm, 1);
            sm += __shfl_xor_sync(0xffffffffu, sm, 2);
            float dinv = 1.0f / sm;
            for (int j = e0; j < deg; j += 4) wbuf[j * NH + h] *= dinv;
        }
        __syncwarp();

        // ---- pass 2: weighted aggregation ----
#pragma unroll 2
        for (int j = 0; j < deg; j++) {
            int s = ps[j];
            const float4* pi4 = (const float4*)(g_Pi + (size_t)s * 256);
            float4 v0 = pi4[lane];
            float4 v1 = pi4[32 + lane];
            float w0 = wbuf[j * NH + hgrp];
            float w1 = wbuf[j * NH + 4 + hgrp];
            acc0.x = fmaf(v0.x, w0, acc0.x);
            acc0.y = fmaf(v0.y, w0, acc0.y);
            acc0.z = fmaf(v0.z, w0, acc0.z);
            acc0.w = fmaf(v0.w, w0, acc0.w);
            acc1.x = fmaf(v1.x, w1, acc1.x);
            acc1.y = fmaf(v1.y, w1, acc1.y);
            acc1.z = fmaf(v1.z, w1, acc1.z);
            acc1.w = fmaf(v1.w, w1, acc1.w);
        }
    }

    float4* o4 = (float4*)(out + (size_t)r * 256);
    o4[lane] = acc0;
    o4[32 + lane] = acc1;
}

// ---------------- launch ----------------
extern "C" void kernel_launch(void* const* d_in, const int* in_sizes, int n_in,
                              void* d_out, int out_size)
{
    const float* nodes     = (const float*)d_in[0];
    const int*   senders   = (const int*)d_in[1];
    const int*   receivers = (const int*)d_in[2];
    const float* Wi        = (const float*)d_in[3];
    const float* bi        = (const float*)d_in[4];
    const float* Wj        = (const float*)d_in[5];
    const float* bj        = (const float*)d_in[6];
    const float* a_w       = (const float*)d_in[7];
    const float* a_b       = (const float*)d_in[8];
    float* out = (float*)d_out;

    static bool attr_set = false;
    if (!attr_set) {
        cudaFuncSetAttribute(gemm_mma, cudaFuncAttributeMaxDynamicSharedMemorySize, 132096);
        attr_set = true;
    }

    init_kernel<<<(NN + 255) / 256, 256>>>();

    presplit_nodes<<<(NN * DIN / 8 + 255) / 256, 256>>>(nodes);
    presplit_W<<<(512 * 256 + 255) / 256, 256>>>(Wi, Wj);

    dim3 gg(4, (NN + 127) / 128);
    gemm_mma<<<gg, 512, 132096>>>(bi, bj);

    hist_kernel<<<(NE + 255) / 256, 256>>>(receivers);
    scan_kernel<<<1, 1024>>>();
    scatter_kernel<<<(NE + 255) / 256, 256>>>(senders, receivers);

    fused_edge_kernel<<<(NN + 7) / 8, 256>>>(a_w, a_b, out);
}